// round 1
// baseline (speedup 1.0000x reference)
#include <cuda_runtime.h>
#include <math.h>

#define Bn   128
#define N1n  128
#define N2n  384
#define Nn   512
#define En   1024
#define DIN  64
#define DFC  128
#define NCHUNK 16
#define ROWS_PER_CHUNK (Nn / NCHUNK)   // 32

// ---------------- device scratch (no allocations allowed) ----------------
__device__ float g_rcpCol[Bn * N2n];         // 1/max(colnorm,1e-12)
__device__ float g_rcpRow[Bn * N1n];         // 1/max(rownorm,1e-12)
__device__ float g_e2T[(size_t)Bn * N2n * N1n]; // exp(-att^T / rownorm), 25 MB
__device__ float g_topP[Bn * NCHUNK];
__device__ float g_botP[Bn * NCHUNK];
__device__ float g_rmsd[Bn];
__device__ float g_cen[Bn];
__device__ float g_pair[Bn];

// ---------------- helpers ----------------
__device__ __forceinline__ float blockSum128(float v, float* red) {
    int t = threadIdx.x;
    red[t] = v; __syncthreads();
    #pragma unroll
    for (int s = 64; s > 0; s >>= 1) {
        if (t < s) red[t] += red[t + s];
        __syncthreads();
    }
    float r = red[0];
    __syncthreads();
    return r;
}

// ---------------- kernel 1: pooled + MLP + sigmoid scores ----------------
__global__ void k_pool_mlp(const float* __restrict__ c_hs,
                           const float* __restrict__ c_valid,
                           const float* __restrict__ W0, const float* __restrict__ b0,
                           const float* __restrict__ W1, const float* __restrict__ b1,
                           const float* __restrict__ W2, const float* __restrict__ b2,
                           const float* __restrict__ W3, const float* __restrict__ b3,
                           float* __restrict__ out) {
    int b = blockIdx.x;
    int t = threadIdx.x;               // 128 threads
    __shared__ float pooled[DIN];
    __shared__ float h1[DFC];
    __shared__ float h2s[DFC];
    __shared__ float red[DFC];

    int d = t & 63, half = t >> 6;
    float acc = 0.f;
    const float* base = c_hs + (size_t)b * Nn * DIN;
    const float* cv = c_valid + (size_t)b * Nn;
    for (int n = half; n < Nn; n += 2)
        acc = fmaf(base[(size_t)n * DIN + d], cv[n], acc);
    red[t] = acc; __syncthreads();
    if (t < 64) pooled[t] = (red[t] + red[t + 64]) * (1.0f / 128.0f);
    __syncthreads();

    float a = b0[t];
    #pragma unroll 8
    for (int k = 0; k < DIN; k++) a = fmaf(pooled[k], W0[k * DFC + t], a);
    h1[t] = fmaxf(a, 0.f);
    __syncthreads();

    a = b1[t];
    #pragma unroll 8
    for (int k = 0; k < DFC; k++) a = fmaf(h1[k], W1[k * DFC + t], a);
    h2s[t] = fmaxf(a, 0.f);
    __syncthreads();

    a = b2[t];
    #pragma unroll 8
    for (int k = 0; k < DFC; k++) a = fmaf(h2s[k], W2[k * DFC + t], a);
    float h3 = fmaxf(a, 0.f);

    red[t] = h3 * W3[t];
    __syncthreads();
    #pragma unroll
    for (int s = 64; s > 0; s >>= 1) {
        if (t < s) red[t] += red[t + s];
        __syncthreads();
    }
    if (t == 0) out[b] = 1.0f / (1.0f + expf(-(red[0] + b3[0])));
}

// ---------------- kernel 2: column & row reciprocal norms ----------------
__global__ void k_norms(const float* __restrict__ att) {
    int b = blockIdx.x;
    int t = threadIdx.x;               // 384 threads
    const float* ab = att + (size_t)b * N1n * N2n;

    float acc = 0.f;
    for (int i = 0; i < N1n; i++) {
        float v = ab[(size_t)i * N2n + t];
        acc = fmaf(v, v, acc);
    }
    g_rcpCol[b * N2n + t] = 1.0f / fmaxf(sqrtf(acc), 1e-12f);

    int w = t >> 5, lane = t & 31;     // 12 warps
    for (int j = w; j < N1n; j += 12) {
        float s = 0.f;
        for (int k = lane; k < N2n; k += 32) {
            float v = ab[(size_t)j * N2n + k];
            s = fmaf(v, v, s);
        }
        #pragma unroll
        for (int o = 16; o; o >>= 1) s += __shfl_xor_sync(0xffffffffu, s, o);
        if (lane == 0) g_rcpRow[b * N1n + j] = 1.0f / fmaxf(sqrtf(s), 1e-12f);
    }
}

// ---------------- kernel 3: transposed exp table e2T[b,k,j] ----------------
__global__ void k_e2T(const float* __restrict__ att) {
    __shared__ float tile[32][33];
    int b = blockIdx.z;
    int kt = blockIdx.x;               // 12 tiles of k
    int jt = blockIdx.y;               // 4 tiles of j
    int tx = threadIdx.x, ty = threadIdx.y;   // 32 x 8
    const float* ab = att + (size_t)b * N1n * N2n;
    #pragma unroll
    for (int m = 0; m < 4; m++) {
        int j = jt * 32 + ty + m * 8;
        int k = kt * 32 + tx;
        float v = ab[(size_t)j * N2n + k];
        tile[ty + m * 8][tx] = __expf(-v * g_rcpRow[b * N1n + j]);
    }
    __syncthreads();
    #pragma unroll
    for (int m = 0; m < 4; m++) {
        int k = kt * 32 + ty + m * 8;
        int j = jt * 32 + tx;
        g_e2T[((size_t)b * N2n + k) * N1n + j] = tile[tx][ty + m * 8];
    }
}

// ---------------- kernel 4: masked-exp attention loss partials ----------------
__global__ void k_loss(const float* __restrict__ att,
                       const float* __restrict__ mapping,
                       const float* __restrict__ samelb) {
    int b = blockIdx.y, chunk = blockIdx.x;
    int t = threadIdx.x;               // 256 threads
    int rl = t >> 7;                   // row within pair
    int j4 = t & 127;                  // float4 lane over 512 cols
    float top = 0.f, bot = 0.f;

    const float4* mp = (const float4*)(mapping + (size_t)b * Nn * Nn);
    const float4* sl = (const float4*)(samelb + (size_t)b * Nn * Nn);

    for (int ii = 0; ii < ROWS_PER_CHUNK; ii += 2) {
        int i = chunk * ROWS_PER_CHUNK + ii + rl;
        float4 m = mp[(size_t)i * 128 + j4];
        float4 s = sl[(size_t)i * 128 + j4];
        float4 e;
        if (i < N1n) {
            if (j4 >= 32) {            // top-right block: att[b,i,j-128]/colnorm
                const float4* ar = (const float4*)(att + ((size_t)b * N1n + i) * N2n);
                const float4* rc = (const float4*)(g_rcpCol + b * N2n);
                float4 av = ar[j4 - 32];
                float4 rv = rc[j4 - 32];
                e.x = __expf(-av.x * rv.x); e.y = __expf(-av.y * rv.y);
                e.z = __expf(-av.z * rv.z); e.w = __expf(-av.w * rv.w);
            } else {
                e = make_float4(1.f, 1.f, 1.f, 1.f);   // zero block -> exp(0)
            }
        } else {
            if (j4 < 32) {             // bottom-left: precomputed transposed exp
                const float4* er = (const float4*)(g_e2T + ((size_t)b * N2n + (i - N1n)) * N1n);
                e = er[j4];
            } else {
                e = make_float4(1.f, 1.f, 1.f, 1.f);
            }
        }
        top = fmaf(m.x, e.x, top); top = fmaf(m.y, e.y, top);
        top = fmaf(m.z, e.z, top); top = fmaf(m.w, e.w, top);
        bot = fmaf(s.x, e.x, bot); bot = fmaf(s.y, e.y, bot);
        bot = fmaf(s.z, e.z, bot); bot = fmaf(s.w, e.w, bot);
    }

    __shared__ float rt[256], rb[256];
    rt[t] = top; rb[t] = bot; __syncthreads();
    #pragma unroll
    for (int sft = 128; sft > 0; sft >>= 1) {
        if (t < sft) { rt[t] += rt[t + sft]; rb[t] += rb[t + sft]; }
        __syncthreads();
    }
    if (t == 0) {
        g_topP[b * NCHUNK + chunk] = rt[0];
        g_botP[b * NCHUNK + chunk] = rb[0];
    }
}

// ---------------- kernel 5: argmax + Kabsch per batch ----------------
__global__ void k_kabsch(const float* __restrict__ att,
                         const float* __restrict__ coords,
                         const float* __restrict__ upd,
                         const float* __restrict__ nm) {
    int b = blockIdx.x, t = threadIdx.x;    // 128 threads, thread = row i
    __shared__ float red[128];
    __shared__ float sh[12];                // r(9) + trans(3)

    // argmax over attention row (first max kept: strict >)
    const float* ar = att + ((size_t)b * N1n + t) * N2n;
    float mx = -1e30f; int am = 0;
    for (int k = 0; k < N2n; k++) {
        float v = ar[k];
        if (v > mx) { mx = v; am = k; }
    }

    const float* pu = upd + ((size_t)b * Nn + t) * 3;
    float px = pu[0], py = pu[1], pz = pu[2];
    const float* qc = coords + ((size_t)b * Nn + N1n + am) * 3;
    float qx = qc[0], qy = qc[1], qz = qc[2];

    float pmx = blockSum128(px, red) * (1.f / 128.f);
    float pmy = blockSum128(py, red) * (1.f / 128.f);
    float pmz = blockSum128(pz, red) * (1.f / 128.f);
    float qmx = blockSum128(qx, red) * (1.f / 128.f);
    float qmy = blockSum128(qy, red) * (1.f / 128.f);
    float qmz = blockSum128(qz, red) * (1.f / 128.f);

    float cx = px - pmx, cy = py - pmy, cz = pz - pmz;
    float dx = qx - qmx, dy = qy - qmy, dz = qz - qmz;

    float h00 = blockSum128(cx * dx, red) * 0.125f;
    float h01 = blockSum128(cx * dy, red) * 0.125f;
    float h02 = blockSum128(cx * dz, red) * 0.125f;
    float h10 = blockSum128(cy * dx, red) * 0.125f;
    float h11 = blockSum128(cy * dy, red) * 0.125f;
    float h12 = blockSum128(cy * dz, red) * 0.125f;
    float h20 = blockSum128(cz * dx, red) * 0.125f;
    float h21 = blockSum128(cz * dy, red) * 0.125f;
    float h22 = blockSum128(cz * dz, red) * 0.125f;

    if (t == 0) {
        double H[3][3] = {{h00, h01, h02}, {h10, h11, h12}, {h20, h21, h22}};
        // K = H^T H  (symmetric PSD)
        double K[3][3];
        for (int a = 0; a < 3; a++)
            for (int c = 0; c < 3; c++) {
                double s = 0;
                for (int r = 0; r < 3; r++) s += H[r][a] * H[r][c];
                K[a][c] = s;
            }
        double V[3][3] = {{1, 0, 0}, {0, 1, 0}, {0, 0, 1}};
        // cyclic Jacobi
        for (int sweep = 0; sweep < 20; sweep++) {
            for (int pi = 0; pi < 3; pi++) {
                int p = (pi == 0) ? 0 : (pi == 1) ? 0 : 1;
                int q = (pi == 0) ? 1 : (pi == 1) ? 2 : 2;
                double apq = K[p][q];
                if (fabs(apq) < 1e-300) continue;
                double theta = (K[q][q] - K[p][p]) / (2.0 * apq);
                double tt = ((theta >= 0) ? 1.0 : -1.0) / (fabs(theta) + sqrt(theta * theta + 1.0));
                double c = 1.0 / sqrt(tt * tt + 1.0);
                double s = tt * c;
                for (int r = 0; r < 3; r++) {          // J^T * K (rows)
                    double kp = K[p][r], kq = K[q][r];
                    K[p][r] = c * kp - s * kq;
                    K[q][r] = s * kp + c * kq;
                }
                for (int r = 0; r < 3; r++) {          // ( ) * J (cols), V = V*J
                    double kp = K[r][p], kq = K[r][q];
                    K[r][p] = c * kp - s * kq;
                    K[r][q] = s * kp + c * kq;
                    double vp = V[r][p], vq = V[r][q];
                    V[r][p] = c * vp - s * vq;
                    V[r][q] = s * vp + c * vq;
                }
            }
        }
        double lam[3] = {K[0][0], K[1][1], K[2][2]};
        // sort descending, carry V columns
        for (int a = 0; a < 2; a++)
            for (int c = a + 1; c < 3; c++)
                if (lam[c] > lam[a]) {
                    double tmp = lam[a]; lam[a] = lam[c]; lam[c] = tmp;
                    for (int r = 0; r < 3; r++) {
                        double tv = V[r][a]; V[r][a] = V[r][c]; V[r][c] = tv;
                    }
                }
        double s0 = sqrt(fmax(lam[0], 0.0));
        double s1 = sqrt(fmax(lam[1], 0.0));
        double s2 = sqrt(fmax(lam[2], 0.0));
        s0 = fmax(s0, 1e-30); s1 = fmax(s1, 1e-30); s2 = fmax(s2, 1e-30);
        double det = H[0][0] * (H[1][1] * H[2][2] - H[1][2] * H[2][1])
                   - H[0][1] * (H[1][0] * H[2][2] - H[1][2] * H[2][0])
                   + H[0][2] * (H[1][0] * H[2][1] - H[1][1] * H[2][0]);
        double d = (det > 0) ? 1.0 : ((det < 0) ? -1.0 : 0.0);
        double g[3] = {1.0 / s0, 1.0 / s1, d / s2};
        // M = V diag(g) V^T ;  R = H M   (== U diag(1,1,d) V^T)
        double M[3][3];
        for (int a = 0; a < 3; a++)
            for (int c = 0; c < 3; c++)
                M[a][c] = V[a][0] * g[0] * V[c][0] + V[a][1] * g[1] * V[c][1] + V[a][2] * g[2] * V[c][2];
        double R[3][3];
        for (int a = 0; a < 3; a++)
            for (int c = 0; c < 3; c++)
                R[a][c] = H[a][0] * M[0][c] + H[a][1] * M[1][c] + H[a][2] * M[2][c];
        double Pm[3] = {pmx, pmy, pmz};
        double Qm[3] = {qmx, qmy, qmz};
        for (int a = 0; a < 3; a++) {
            sh[a * 3 + 0] = (float)R[a][0];
            sh[a * 3 + 1] = (float)R[a][1];
            sh[a * 3 + 2] = (float)R[a][2];
            sh[9 + a] = (float)(Qm[a] - (R[a][0] * Pm[0] + R[a][1] * Pm[1] + R[a][2] * Pm[2]));
        }
    }
    __syncthreads();

    float ppx = sh[0] * px + sh[1] * py + sh[2] * pz + sh[9];
    float ppy = sh[3] * px + sh[4] * py + sh[5] * pz + sh[10];
    float ppz = sh[6] * px + sh[7] * py + sh[8] * pz + sh[11];
    float mk = (nm[b * N1n + t] > 0.5f) ? 1.f : 0.f;
    float ex = ppx - qx, ey = ppy - qy, ez = ppz - qz;
    float sq = mk * (ex * ex + ey * ey + ez * ez);

    float sqs  = blockSum128(sq, red);
    float cnt  = blockSum128(mk, red);
    float pax  = blockSum128(ppx, red) * (1.f / 128.f);
    float pay  = blockSum128(ppy, red) * (1.f / 128.f);
    float paz  = blockSum128(ppz, red) * (1.f / 128.f);

    if (t == 0) {
        float cc = fmaxf(cnt * 3.0f, 1.0f);
        g_rmsd[b] = sqs / cc;
        float gx = pax - qmx, gy = pay - qmy, gz = paz - qmz;
        g_cen[b] = (gx * gx + gy * gy + gz * gz) * (1.f / 3.f);
    }
}

// ---------------- kernel 6: pair-distance loss ----------------
__global__ void k_pair(const float* __restrict__ coords,
                       const float* __restrict__ upd,
                       const int* __restrict__ edge) {
    int b = blockIdx.x, t = threadIdx.x;    // 256 threads
    __shared__ float red[256];
    const float* cb = coords + (size_t)b * Nn * 3;
    const float* ub = upd + (size_t)b * Nn * 3;
    const int* eb = edge + (size_t)b * En * 2;
    float acc = 0.f;
    for (int e = t; e < En; e += 256) {
        int i0 = eb[e * 2], i1 = eb[e * 2 + 1];
        float ax = cb[i0 * 3] - cb[i1 * 3];
        float ay = cb[i0 * 3 + 1] - cb[i1 * 3 + 1];
        float az = cb[i0 * 3 + 2] - cb[i1 * 3 + 2];
        float d0 = sqrtf(ax * ax + ay * ay + az * az + 1e-12f);
        float bx = ub[i0 * 3] - ub[i1 * 3];
        float by = ub[i0 * 3 + 1] - ub[i1 * 3 + 1];
        float bz = ub[i0 * 3 + 2] - ub[i1 * 3 + 2];
        float d1 = sqrtf(bx * bx + by * by + bz * bz + 1e-12f);
        acc += (d1 - d0);
    }
    red[t] = acc; __syncthreads();
    #pragma unroll
    for (int s = 128; s > 0; s >>= 1) {
        if (t < s) red[t] += red[t + s];
        __syncthreads();
    }
    if (t == 0) g_pair[b] = fabsf(red[0]);
}

// ---------------- kernel 7: finalize scalars ----------------
__global__ void k_final(float* __restrict__ out) {
    __shared__ float red[128];
    int t = threadIdx.x;                // 128 threads, t = batch
    float top = 0.f, bot = 0.f;
    for (int c = 0; c < NCHUNK; c++) {
        top += g_topP[t * NCHUNK + c];
        bot += g_botP[t * NCHUNK + c];
    }
    float term = top / (bot - top + 1.0f);
    float aL = blockSum128(term, red) * (1.f / 128.f);
    float rL = blockSum128(g_rmsd[t], red) * (1.f / 128.f);
    float pL = blockSum128(g_pair[t], red) * (1.f / 128.f);
    float cL = blockSum128(g_cen[t], red) * (1.f / 128.f);
    if (t == 0) {
        out[128] = aL;   // attn_loss
        out[129] = rL;   // rmsd_loss
        out[130] = pL;   // pairdst_loss
        out[131] = cL;   // centroid_loss
    }
}

// ---------------- launch ----------------
extern "C" void kernel_launch(void* const* d_in, const int* in_sizes, int n_in,
                              void* d_out, int out_size) {
    const float* c_hs      = (const float*)d_in[0];
    const float* attention = (const float*)d_in[1];
    const float* coords    = (const float*)d_in[2];
    const float* upd       = (const float*)d_in[3];
    const float* c_valid   = (const float*)d_in[4];
    const float* nm        = (const float*)d_in[5];
    const float* mapping   = (const float*)d_in[6];
    const float* samelb    = (const float*)d_in[7];
    const int*   edge      = (const int*)d_in[8];
    const float* W0 = (const float*)d_in[9];
    const float* b0 = (const float*)d_in[10];
    const float* W1 = (const float*)d_in[11];
    const float* b1 = (const float*)d_in[12];
    const float* W2 = (const float*)d_in[13];
    const float* b2 = (const float*)d_in[14];
    const float* W3 = (const float*)d_in[15];
    const float* b3 = (const float*)d_in[16];
    float* out = (float*)d_out;

    k_pool_mlp<<<Bn, 128>>>(c_hs, c_valid, W0, b0, W1, b1, W2, b2, W3, b3, out);
    k_norms<<<Bn, N2n>>>(attention);
    k_e2T<<<dim3(12, 4, Bn), dim3(32, 8)>>>(attention);
    k_loss<<<dim3(NCHUNK, Bn), 256>>>(attention, mapping, samelb);
    k_kabsch<<<Bn, 128>>>(attention, coords, upd, nm);
    k_pair<<<Bn, 256>>>(coords, upd, edge);
    k_final<<<1, 128>>>(out);
}

// round 3
// speedup vs baseline: 3.4209x; 3.4209x over previous
#include <cuda_runtime.h>
#include <math.h>

#define Bn   128
#define N1n  128
#define N2n  384
#define Nn   512
#define En   1024
#define DIN  64
#define DFC  128
#define NCHUNK 16
#define ROWS_PER_CHUNK (Nn / NCHUNK)   // 32

// ---------------- device scratch (no allocations allowed) ----------------
__device__ float g_rcpCol[Bn * N2n];         // 1/max(colnorm,1e-12)
__device__ float g_rcpRow[Bn * N1n];         // 1/max(rownorm,1e-12)
__device__ int   g_am[Bn * N1n];             // per-row argmax of attention
__device__ float g_topP[Bn * NCHUNK];
__device__ float g_botP[Bn * NCHUNK];
__device__ float g_rmsd[Bn];
__device__ float g_cen[Bn];
__device__ float g_pair[Bn];

// ---------------- helpers ----------------
__device__ __forceinline__ float bsum128(float v, float* sw) {
    // 128 threads: warp shuffle reduce + 4-way smem combine (2 syncs)
    int t = threadIdx.x, lane = t & 31, w = t >> 5;
    #pragma unroll
    for (int o = 16; o; o >>= 1) v += __shfl_xor_sync(0xffffffffu, v, o);
    __syncthreads();
    if (lane == 0) sw[w] = v;
    __syncthreads();
    return sw[0] + sw[1] + sw[2] + sw[3];
}

// ---------------- kernel 1: pooled + MLP + sigmoid scores ----------------
__global__ void k_pool_mlp(const float* __restrict__ c_hs,
                           const float* __restrict__ c_valid,
                           const float* __restrict__ W0, const float* __restrict__ b0,
                           const float* __restrict__ W1, const float* __restrict__ b1,
                           const float* __restrict__ W2, const float* __restrict__ b2,
                           const float* __restrict__ W3, const float* __restrict__ b3,
                           float* __restrict__ out) {
    int b = blockIdx.x;
    int t = threadIdx.x;               // 128 threads
    __shared__ float pooled[DIN];
    __shared__ float h1[DFC];
    __shared__ float h2s[DFC];
    __shared__ float red[DFC];

    int d = t & 63, half = t >> 6;
    float acc = 0.f;
    const float* base = c_hs + (size_t)b * Nn * DIN;
    const float* cv = c_valid + (size_t)b * Nn;
    #pragma unroll 4
    for (int n = half; n < Nn; n += 2)
        acc = fmaf(base[(size_t)n * DIN + d], cv[n], acc);
    red[t] = acc; __syncthreads();
    if (t < 64) pooled[t] = (red[t] + red[t + 64]) * (1.0f / 128.0f);
    __syncthreads();

    float a = b0[t];
    #pragma unroll 8
    for (int k = 0; k < DIN; k++) a = fmaf(pooled[k], W0[k * DFC + t], a);
    h1[t] = fmaxf(a, 0.f);
    __syncthreads();

    a = b1[t];
    #pragma unroll 8
    for (int k = 0; k < DFC; k++) a = fmaf(h1[k], W1[k * DFC + t], a);
    h2s[t] = fmaxf(a, 0.f);
    __syncthreads();

    a = b2[t];
    #pragma unroll 8
    for (int k = 0; k < DFC; k++) a = fmaf(h2s[k], W2[k * DFC + t], a);
    float h3 = fmaxf(a, 0.f);

    red[t] = h3 * W3[t];
    __syncthreads();
    #pragma unroll
    for (int s = 64; s > 0; s >>= 1) {
        if (t < s) red[t] += red[t + s];
        __syncthreads();
    }
    if (t == 0) out[b] = 1.0f / (1.0f + expf(-(red[0] + b3[0])));
}

// ---------------- kernel 2: norms + per-row argmax (all coalesced) ------
__global__ void k_prep(const float* __restrict__ att) {
    int b = blockIdx.x;
    int t = threadIdx.x;               // 384 threads = 12 warps
    int w = t >> 5, lane = t & 31;
    const float* ab = att + (size_t)b * N1n * N2n;

    // row sumsq + argmax: warp per row, lane-strided cols (coalesced)
    for (int j = w; j < N1n; j += 12) {
        const float* row = ab + (size_t)j * N2n;
        float s = 0.f;
        float mx = -1e30f; int am = 0;
        for (int k = lane; k < N2n; k += 32) {
            float v = row[k];
            s = fmaf(v, v, s);
            if (v > mx) { mx = v; am = k; }
        }
        #pragma unroll
        for (int o = 16; o; o >>= 1) {
            s += __shfl_xor_sync(0xffffffffu, s, o);
            float omx = __shfl_xor_sync(0xffffffffu, mx, o);
            int   oam = __shfl_xor_sync(0xffffffffu, am, o);
            if (omx > mx || (omx == mx && oam < am)) { mx = omx; am = oam; }
        }
        if (lane == 0) {
            g_rcpRow[b * N1n + j] = 1.0f / fmaxf(sqrtf(s), 1e-12f);
            g_am[b * N1n + j] = am;
        }
    }

    // col sumsq: thread per col (coalesced across threads), rows hot in L2
    float acc0 = 0.f, acc1 = 0.f, acc2 = 0.f, acc3 = 0.f;
    #pragma unroll 4
    for (int i = 0; i < N1n; i += 4) {
        float v0 = ab[(size_t)(i + 0) * N2n + t];
        float v1 = ab[(size_t)(i + 1) * N2n + t];
        float v2 = ab[(size_t)(i + 2) * N2n + t];
        float v3 = ab[(size_t)(i + 3) * N2n + t];
        acc0 = fmaf(v0, v0, acc0); acc1 = fmaf(v1, v1, acc1);
        acc2 = fmaf(v2, v2, acc2); acc3 = fmaf(v3, v3, acc3);
    }
    float acc = (acc0 + acc1) + (acc2 + acc3);
    g_rcpCol[b * N2n + t] = 1.0f / fmaxf(sqrtf(acc), 1e-12f);
}

// ---------------- kernel 3: masked-exp attention loss partials ----------
__global__ void k_loss(const float* __restrict__ att,
                       const float* __restrict__ mapping,
                       const float* __restrict__ samelb) {
    int b = blockIdx.y, chunk = blockIdx.x;
    int t = threadIdx.x;               // 256 threads
    int rl = t >> 7;                   // row within pair
    int j4 = t & 127;                  // float4 lane over 512 cols
    float top = 0.f, bot = 0.f;

    const float4* mp = (const float4*)(mapping + (size_t)b * Nn * Nn);
    const float4* sl = (const float4*)(samelb + (size_t)b * Nn * Nn);

    for (int ii = 0; ii < ROWS_PER_CHUNK; ii += 2) {
        int i = chunk * ROWS_PER_CHUNK + ii + rl;
        float4 m = __ldcs(&mp[(size_t)i * 128 + j4]);
        float4 s = __ldcs(&sl[(size_t)i * 128 + j4]);
        float4 e;
        if (i < N1n) {
            if (j4 >= 32) {            // top-right block: att[b,i,j-128]/colnorm
                const float4* ar = (const float4*)(att + ((size_t)b * N1n + i) * N2n);
                const float4* rc = (const float4*)(g_rcpCol + b * N2n);
                float4 av = __ldg(&ar[j4 - 32]);
                float4 rv = __ldg(&rc[j4 - 32]);
                e.x = __expf(-av.x * rv.x); e.y = __expf(-av.y * rv.y);
                e.z = __expf(-av.z * rv.z); e.w = __expf(-av.w * rv.w);
            } else {
                e = make_float4(1.f, 1.f, 1.f, 1.f);   // zero block -> exp(0)
            }
        } else {
            if (j4 < 32) {             // bottom-left: transposed att read (L2-hot)
                int col = i - N1n;     // column of att, consecutive across ii
                int j = j4 * 4;
                const float* abase = att + (size_t)b * N1n * N2n + col;
                float4 rv = __ldg((const float4*)(g_rcpRow + b * N1n) + j4);
                float a0 = __ldg(abase + (size_t)(j + 0) * N2n);
                float a1 = __ldg(abase + (size_t)(j + 1) * N2n);
                float a2 = __ldg(abase + (size_t)(j + 2) * N2n);
                float a3 = __ldg(abase + (size_t)(j + 3) * N2n);
                e.x = __expf(-a0 * rv.x); e.y = __expf(-a1 * rv.y);
                e.z = __expf(-a2 * rv.z); e.w = __expf(-a3 * rv.w);
            } else {
                e = make_float4(1.f, 1.f, 1.f, 1.f);
            }
        }
        top = fmaf(m.x, e.x, top); top = fmaf(m.y, e.y, top);
        top = fmaf(m.z, e.z, top); top = fmaf(m.w, e.w, top);
        bot = fmaf(s.x, e.x, bot); bot = fmaf(s.y, e.y, bot);
        bot = fmaf(s.z, e.z, bot); bot = fmaf(s.w, e.w, bot);
    }

    __shared__ float rt[256], rb[256];
    rt[t] = top; rb[t] = bot; __syncthreads();
    #pragma unroll
    for (int sft = 128; sft > 0; sft >>= 1) {
        if (t < sft) { rt[t] += rt[t + sft]; rb[t] += rb[t + sft]; }
        __syncthreads();
    }
    if (t == 0) {
        g_topP[b * NCHUNK + chunk] = rt[0];
        g_botP[b * NCHUNK + chunk] = rb[0];
    }
}

// ---------------- kernel 4: Kabsch per batch (argmax precomputed) -------
__global__ void k_kabsch(const float* __restrict__ coords,
                         const float* __restrict__ upd,
                         const float* __restrict__ nm) {
    int b = blockIdx.x, t = threadIdx.x;    // 128 threads, thread = row i
    __shared__ float sw[4];
    __shared__ float sh[12];                // r(9) + trans(3)

    int am = g_am[b * N1n + t];

    const float* pu = upd + ((size_t)b * Nn + t) * 3;
    float px = pu[0], py = pu[1], pz = pu[2];
    const float* qc = coords + ((size_t)b * Nn + N1n + am) * 3;
    float qx = qc[0], qy = qc[1], qz = qc[2];

    float pmx = bsum128(px, sw) * (1.f / 128.f);
    float pmy = bsum128(py, sw) * (1.f / 128.f);
    float pmz = bsum128(pz, sw) * (1.f / 128.f);
    float qmx = bsum128(qx, sw) * (1.f / 128.f);
    float qmy = bsum128(qy, sw) * (1.f / 128.f);
    float qmz = bsum128(qz, sw) * (1.f / 128.f);

    float cx = px - pmx, cy = py - pmy, cz = pz - pmz;
    float dx = qx - qmx, dy = qy - qmy, dz = qz - qmz;

    float h00 = bsum128(cx * dx, sw) * 0.125f;
    float h01 = bsum128(cx * dy, sw) * 0.125f;
    float h02 = bsum128(cx * dz, sw) * 0.125f;
    float h10 = bsum128(cy * dx, sw) * 0.125f;
    float h11 = bsum128(cy * dy, sw) * 0.125f;
    float h12 = bsum128(cy * dz, sw) * 0.125f;
    float h20 = bsum128(cz * dx, sw) * 0.125f;
    float h21 = bsum128(cz * dy, sw) * 0.125f;
    float h22 = bsum128(cz * dz, sw) * 0.125f;

    if (t == 0) {
        float H[3][3] = {{h00, h01, h02}, {h10, h11, h12}, {h20, h21, h22}};
        // K = H^T H  (symmetric PSD)
        float K[3][3];
        #pragma unroll
        for (int a = 0; a < 3; a++)
            #pragma unroll
            for (int c = 0; c < 3; c++) {
                float s = 0;
                #pragma unroll
                for (int r = 0; r < 3; r++) s += H[r][a] * H[r][c];
                K[a][c] = s;
            }
        float V[3][3] = {{1, 0, 0}, {0, 1, 0}, {0, 0, 1}};
        // cyclic Jacobi (fp32, 10 sweeps — 3x3 converges in ~5)
        for (int sweep = 0; sweep < 10; sweep++) {
            #pragma unroll
            for (int pi = 0; pi < 3; pi++) {
                int p = (pi == 0) ? 0 : (pi == 1) ? 0 : 1;
                int q = (pi == 0) ? 1 : (pi == 1) ? 2 : 2;
                float apq = K[p][q];
                if (fabsf(apq) < 1e-30f) continue;
                float theta = (K[q][q] - K[p][p]) / (2.0f * apq);
                float tt = copysignf(1.0f, theta) / (fabsf(theta) + sqrtf(theta * theta + 1.0f));
                float c = rsqrtf(tt * tt + 1.0f);
                float s = tt * c;
                #pragma unroll
                for (int r = 0; r < 3; r++) {          // J^T * K (rows)
                    float kp = K[p][r], kq = K[q][r];
                    K[p][r] = c * kp - s * kq;
                    K[q][r] = s * kp + c * kq;
                }
                #pragma unroll
                for (int r = 0; r < 3; r++) {          // ( ) * J (cols), V = V*J
                    float kp = K[r][p], kq = K[r][q];
                    K[r][p] = c * kp - s * kq;
                    K[r][q] = s * kp + c * kq;
                    float vp = V[r][p], vq = V[r][q];
                    V[r][p] = c * vp - s * vq;
                    V[r][q] = s * vp + c * vq;
                }
            }
        }
        float lam[3] = {K[0][0], K[1][1], K[2][2]};
        #pragma unroll
        for (int a = 0; a < 2; a++)
            #pragma unroll
            for (int c = a + 1; c < 3; c++)
                if (lam[c] > lam[a]) {
                    float tmp = lam[a]; lam[a] = lam[c]; lam[c] = tmp;
                    #pragma unroll
                    for (int r = 0; r < 3; r++) {
                        float tv = V[r][a]; V[r][a] = V[r][c]; V[r][c] = tv;
                    }
                }
        float s0 = fmaxf(sqrtf(fmaxf(lam[0], 0.f)), 1e-20f);
        float s1 = fmaxf(sqrtf(fmaxf(lam[1], 0.f)), 1e-20f);
        float s2 = fmaxf(sqrtf(fmaxf(lam[2], 0.f)), 1e-20f);
        float det = H[0][0] * (H[1][1] * H[2][2] - H[1][2] * H[2][1])
                  - H[0][1] * (H[1][0] * H[2][2] - H[1][2] * H[2][0])
                  + H[0][2] * (H[1][0] * H[2][1] - H[1][1] * H[2][0]);
        float d = (det > 0.f) ? 1.f : ((det < 0.f) ? -1.f : 0.f);
        float g[3] = {1.0f / s0, 1.0f / s1, d / s2};
        // M = V diag(g) V^T ;  R = H M   (== U diag(1,1,d) V^T)
        float M[3][3];
        #pragma unroll
        for (int a = 0; a < 3; a++)
            #pragma unroll
            for (int c = 0; c < 3; c++)
                M[a][c] = V[a][0] * g[0] * V[c][0] + V[a][1] * g[1] * V[c][1] + V[a][2] * g[2] * V[c][2];
        float R[3][3];
        #pragma unroll
        for (int a = 0; a < 3; a++)
            #pragma unroll
            for (int c = 0; c < 3; c++)
                R[a][c] = H[a][0] * M[0][c] + H[a][1] * M[1][c] + H[a][2] * M[2][c];
        float Pm[3] = {pmx, pmy, pmz};
        float Qm[3] = {qmx, qmy, qmz};
        #pragma unroll
        for (int a = 0; a < 3; a++) {
            sh[a * 3 + 0] = R[a][0];
            sh[a * 3 + 1] = R[a][1];
            sh[a * 3 + 2] = R[a][2];
            sh[9 + a] = Qm[a] - (R[a][0] * Pm[0] + R[a][1] * Pm[1] + R[a][2] * Pm[2]);
        }
    }
    __syncthreads();

    float ppx = sh[0] * px + sh[1] * py + sh[2] * pz + sh[9];
    float ppy = sh[3] * px + sh[4] * py + sh[5] * pz + sh[10];
    float ppz = sh[6] * px + sh[7] * py + sh[8] * pz + sh[11];
    float mk = (nm[b * N1n + t] > 0.5f) ? 1.f : 0.f;
    float ex = ppx - qx, ey = ppy - qy, ez = ppz - qz;
    float sq = mk * (ex * ex + ey * ey + ez * ez);

    float sqs  = bsum128(sq, sw);
    float cnt  = bsum128(mk, sw);
    float pax  = bsum128(ppx, sw) * (1.f / 128.f);
    float pay  = bsum128(ppy, sw) * (1.f / 128.f);
    float paz  = bsum128(ppz, sw) * (1.f / 128.f);

    if (t == 0) {
        float cc = fmaxf(cnt * 3.0f, 1.0f);
        g_rmsd[b] = sqs / cc;
        float gx = pax - qmx, gy = pay - qmy, gz = paz - qmz;
        g_cen[b] = (gx * gx + gy * gy + gz * gz) * (1.f / 3.f);
    }
}

// ---------------- kernel 5: pair-distance loss ----------------
__global__ void k_pair(const float* __restrict__ coords,
                       const float* __restrict__ upd,
                       const int* __restrict__ edge) {
    int b = blockIdx.x, t = threadIdx.x;    // 256 threads
    __shared__ float red[256];
    const float* cb = coords + (size_t)b * Nn * 3;
    const float* ub = upd + (size_t)b * Nn * 3;
    const int* eb = edge + (size_t)b * En * 2;
    float acc = 0.f;
    for (int e = t; e < En; e += 256) {
        int i0 = eb[e * 2], i1 = eb[e * 2 + 1];
        float ax = cb[i0 * 3] - cb[i1 * 3];
        float ay = cb[i0 * 3 + 1] - cb[i1 * 3 + 1];
        float az = cb[i0 * 3 + 2] - cb[i1 * 3 + 2];
        float d0 = sqrtf(ax * ax + ay * ay + az * az + 1e-12f);
        float bx = ub[i0 * 3] - ub[i1 * 3];
        float by = ub[i0 * 3 + 1] - ub[i1 * 3 + 1];
        float bz = ub[i0 * 3 + 2] - ub[i1 * 3 + 2];
        float d1 = sqrtf(bx * bx + by * by + bz * bz + 1e-12f);
        acc += (d1 - d0);
    }
    red[t] = acc; __syncthreads();
    #pragma unroll
    for (int s = 128; s > 0; s >>= 1) {
        if (t < s) red[t] += red[t + s];
        __syncthreads();
    }
    if (t == 0) g_pair[b] = fabsf(red[0]);
}

// ---------------- kernel 6: finalize scalars ----------------
__global__ void k_final(float* __restrict__ out) {
    __shared__ float sw[4];
    int t = threadIdx.x;                // 128 threads, t = batch
    float top = 0.f, bot = 0.f;
    #pragma unroll
    for (int c = 0; c < NCHUNK; c++) {
        top += g_topP[t * NCHUNK + c];
        bot += g_botP[t * NCHUNK + c];
    }
    float term = top / (bot - top + 1.0f);
    float aL = bsum128(term, sw) * (1.f / 128.f);
    float rL = bsum128(g_rmsd[t], sw) * (1.f / 128.f);
    float pL = bsum128(g_pair[t], sw) * (1.f / 128.f);
    float cL = bsum128(g_cen[t], sw) * (1.f / 128.f);
    if (t == 0) {
        out[128] = aL;   // attn_loss
        out[129] = rL;   // rmsd_loss
        out[130] = pL;   // pairdst_loss
        out[131] = cL;   // centroid_loss
    }
}

// ---------------- launch ----------------
extern "C" void kernel_launch(void* const* d_in, const int* in_sizes, int n_in,
                              void* d_out, int out_size) {
    const float* c_hs      = (const float*)d_in[0];
    const float* attention = (const float*)d_in[1];
    const float* coords    = (const float*)d_in[2];
    const float* upd       = (const float*)d_in[3];
    const float* c_valid   = (const float*)d_in[4];
    const float* nm        = (const float*)d_in[5];
    const float* mapping   = (const float*)d_in[6];
    const float* samelb    = (const float*)d_in[7];
    const int*   edge      = (const int*)d_in[8];
    const float* W0 = (const float*)d_in[9];
    const float* b0 = (const float*)d_in[10];
    const float* W1 = (const float*)d_in[11];
    const float* b1 = (const float*)d_in[12];
    const float* W2 = (const float*)d_in[13];
    const float* b2 = (const float*)d_in[14];
    const float* W3 = (const float*)d_in[15];
    const float* b3 = (const float*)d_in[16];
    float* out = (float*)d_out;

    k_prep<<<Bn, N2n>>>(attention);
    k_loss<<<dim3(NCHUNK, Bn), 256>>>(attention, mapping, samelb);
    k_pool_mlp<<<Bn, 128>>>(c_hs, c_valid, W0, b0, W1, b1, W2, b2, W3, b3, out);
    k_kabsch<<<Bn, 128>>>(coords, upd, nm);
    k_pair<<<Bn, 256>>>(coords, upd, edge);
    k_final<<<1, 128>>>(out);
}